// round 12
// baseline (speedup 1.0000x reference)
#include <cuda_runtime.h>
#include <cuda_pipeline.h>
#include <math_constants.h>

#define B_ 4
#define T_ 512
#define D_ 128
#define H_ 64
#define KP (H_ + 4)   // padded K row stride (conflict-free f4 phases)

__device__ float g_Q[B_*T_*H_];
__device__ float g_K[B_*T_*H_];

__device__ __forceinline__ float tanh_fast(float x) {
    float y;
    asm("tanh.approx.f32 %0, %1;" : "=f"(y) : "f"(x));
    return y;
}

// ---------------------------------------------------------------------------
// Kernel 1: Q/K' prep (R8 version, unchanged control). grid (T/8,B)=256.
// ---------------------------------------------------------------------------
__global__ __launch_bounds__(256) void prep_kernel(
    const float* __restrict__ input, const float* __restrict__ demo,
    const float* __restrict__ Wt, const float* __restrict__ Wx,
    const float* __restrict__ Wd, const float* __restrict__ bh)
{
    extern __shared__ float dyn[];
    float* sx  = dyn;           // [8][128]
    float* sWt = dyn + 1024;    // [128][64]
    float* sWx = dyn + 9216;    // [128][64]

    const int b   = blockIdx.y;
    const int t0  = blockIdx.x * 8;
    const int tid = threadIdx.x;
    const int h   = tid & 63;
    const int rg  = tid >> 6;

    {
        const float4* gin = (const float4*)(input + (size_t)(b*T_ + t0)*D_);
        __pipeline_memcpy_async(&((float4*)sx)[tid], &gin[tid], 16);
        const float4* gt = (const float4*)Wt;
        const float4* gx = (const float4*)Wx;
        #pragma unroll
        for (int i = 0; i < 8; i++) {
            int idx = tid + 256*i;
            __pipeline_memcpy_async(&((float4*)sWt)[idx], &gt[idx], 16);
            __pipeline_memcpy_async(&((float4*)sWx)[idx], &gx[idx], 16);
        }
        __pipeline_commit();
    }

    float dd = bh[h];
    #pragma unroll
    for (int j = 0; j < 12; j++) dd = fmaf(demo[b*12 + j], Wd[j*H_ + h], dd);

    __pipeline_wait_prior(0);
    __syncthreads();

    float aq0=0.f, ak0=0.f, aq1=0.f, ak1=0.f;
    #pragma unroll 16
    for (int d = 0; d < D_; d++) {
        float wt = sWt[d*H_ + h];
        float wx = sWx[d*H_ + h];
        float x0 = sx[(rg    )*D_ + d];
        float x1 = sx[(rg + 4)*D_ + d];
        aq0 = fmaf(x0, wt, aq0);
        ak0 = fmaf(x0, wx, ak0);
        aq1 = fmaf(x1, wt, aq1);
        ak1 = fmaf(x1, wx, ak1);
    }

    const size_t o0 = (size_t)(b*T_ + t0 + rg    )*H_ + h;
    const size_t o1 = (size_t)(b*T_ + t0 + rg + 4)*H_ + h;
    g_Q[o0] = aq0;  g_K[o0] = ak0 + dd;
    g_Q[o1] = aq1;  g_K[o1] = ak1 + dd;
}

// ---------------------------------------------------------------------------
// Kernel 2: FUSED strip kernel, TT=4. CTA per (b, 4-row t-strip), 256 thr,
// grid (128, 4) = 512 CTAs, heavy-first. ~27KB smem -> ~3.5 CTAs/SM resident.
// Phase 1: causal scores, 64-s chunks (nk = t0/64+1), thread = one (t,s).
// Phase 2: causal softmax (4 warps, one per row), P -> out_e + sSc.
// Phase 3: v = P @ input, warp PAIR per row (parity split over s).
// ---------------------------------------------------------------------------
__global__ __launch_bounds__(256, 7) void strip_kernel(
    const float* __restrict__ input,
    const float* __restrict__ Wa, const float* __restrict__ ba,
    float* __restrict__ out_e, float* __restrict__ out_v)
{
    __shared__ float sQ[4][H_];        // 1 KB
    __shared__ float sWa[H_];
    __shared__ float sK[64][KP];       // 17.4 KB (reused as input stage)
    __shared__ float sSc[4][T_];       // 8 KB
    __shared__ float sVp[4][D_];       // 2 KB partials

    const int b    = blockIdx.y;
    const int strip = 127 - (int)blockIdx.x;   // heavy first
    const int t0   = strip * 4;
    const int tid  = threadIdx.x;

    {   // Q strip (4 rows = 64 f4) + Wa
        if (tid < 64) {
            const float4* gq = (const float4*)(g_Q + (size_t)(b*T_ + t0)*H_);
            ((float4*)sQ)[tid] = gq[tid];
        } else if (tid < 64 + H_/4) {
            ((float4*)sWa)[tid - 64] = ((const float4*)Wa)[tid - 64];
        }
    }
    const float bav = ba[0];

    // ---- Phase 1: scores over nk 64-s chunks ----
    const int nk = t0/64 + 1;          // 1..8
    const int sl = tid & 63;           // this thread's s within chunk
    const int tg = tid >> 6;           // this thread's t-row (warp-uniform)
    const int j4 = tid & 15;
    const int r4 = tid >> 4;           // 16 K rows per pass

    for (int c = 0; c < nk; c++) {
        __syncthreads();               // sK free (first iter: covers sQ/sWa)
        {
            const float4* kp = (const float4*)(g_K + (size_t)(b*T_ + c*64)*H_);
            #pragma unroll
            for (int ii = 0; ii < 4; ii++) {
                int r = r4 + 16*ii;
                __pipeline_memcpy_async(&sK[r][4*j4], &kp[(size_t)r*16 + j4], 16);
            }
            __pipeline_commit();
        }
        __pipeline_wait_prior(0);
        __syncthreads();

        float a0=0.f, a1=0.f, a2=0.f, a3=0.f;
        #pragma unroll
        for (int h4 = 0; h4 < H_/4; h4++) {
            float4 k = *(const float4*)&sK[sl][4*h4];
            float4 w = ((const float4*)sWa)[h4];
            float4 q = ((const float4*)sQ[tg])[h4];
            a0 = fmaf(w.x, tanh_fast(q.x + k.x), a0);
            a1 = fmaf(w.y, tanh_fast(q.y + k.y), a1);
            a2 = fmaf(w.z, tanh_fast(q.z + k.z), a2);
            a3 = fmaf(w.w, tanh_fast(q.w + k.w), a3);
        }
        sSc[tg][c*64 + sl] = bav + ((a0 + a1) + (a2 + a3));
    }
    __syncthreads();

    const int w    = tid >> 5;
    const int lane = tid & 31;

    // ---- Phase 2: causal softmax, warps 0-3 own rows 0-3 ----
    if (w < 4) {
        const int t = t0 + w;
        float vals[T_/32];
        float m = -CUDART_INF_F;
        #pragma unroll
        for (int i = 0; i < T_/32; i++) {
            int s = lane + 32*i;
            vals[i] = (s <= t) ? sSc[w][s] : -CUDART_INF_F;
            m = fmaxf(m, vals[i]);
        }
        #pragma unroll
        for (int off = 16; off; off >>= 1) m = fmaxf(m, __shfl_xor_sync(0xffffffffu, m, off));
        float sum = 0.f;
        #pragma unroll
        for (int i = 0; i < T_/32; i++) {
            float e = __expf(vals[i] - m);   // -inf -> 0
            vals[i] = e;
            sum += e;
        }
        #pragma unroll
        for (int off = 16; off; off >>= 1) sum += __shfl_xor_sync(0xffffffffu, sum, off);
        float inv = 1.f / (sum + 1e-7f);
        float* ge = out_e + ((size_t)(b*T_ + t))*T_;
        #pragma unroll
        for (int i = 0; i < T_/32; i++) {
            int s = lane + 32*i;
            float p = vals[i] * inv;         // 0 for s>t
            ge[s]     = p;
            sSc[w][s] = p;
        }
    }
    __syncthreads();

    // ---- Phase 3: v, warp pair (row, row+4 parity) over causal chunks ----
    const int row = w & 3;
    const int pr  = w >> 2;            // parity over s
    const int nc  = t0/32 + 1;         // 1..16
    float* sIn = &sK[0][0];            // 32 x 128 floats
    float4 acc = make_float4(0.f,0.f,0.f,0.f);
    for (int c = 0; c < nc; c++) {
        __syncthreads();
        {
            const float4* gin = (const float4*)(input + (size_t)(b*T_ + c*32)*D_);
            #pragma unroll
            for (int ii = 0; ii < 4; ii++) ((float4*)sIn)[tid + 256*ii] = gin[tid + 256*ii];
        }
        __syncthreads();
        #pragma unroll
        for (int k = 0; k < 16; k++) {
            int s = 2*k + pr;
            float p = sSc[row][c*32 + s];
            float4 x = ((const float4*)(sIn + s*D_))[lane];
            acc.x = fmaf(p, x.x, acc.x);
            acc.y = fmaf(p, x.y, acc.y);
            acc.z = fmaf(p, x.z, acc.z);
            acc.w = fmaf(p, x.w, acc.w);
        }
    }
    __syncthreads();
    if (pr == 1) *(float4*)&sVp[row][4*lane] = acc;
    __syncthreads();
    if (pr == 0) {
        float4 o = *(const float4*)&sVp[row][4*lane];
        o.x += acc.x; o.y += acc.y; o.z += acc.z; o.w += acc.w;
        ((float4*)(out_v + (size_t)(b*T_ + t0 + row)*D_))[lane] = o;
    }
}

// ---------------------------------------------------------------------------
extern "C" void kernel_launch(void* const* d_in, const int* in_sizes, int n_in,
                              void* d_out, int out_size)
{
    const float* input = (const float*)d_in[0];
    const float* demo  = (const float*)d_in[1];
    const float* Wt    = (const float*)d_in[2];
    const float* Wx    = (const float*)d_in[3];
    const float* Wd    = (const float*)d_in[4];
    const float* bh    = (const float*)d_in[5];
    const float* Wa    = (const float*)d_in[6];
    const float* ba    = (const float*)d_in[7];

    float* out_v = (float*)d_out;                   // [B,T,D]
    float* out_e = out_v + (size_t)B_ * T_ * D_;    // [B,T,T]

    static int smem_set = 0;
    const int prep_smem = (1024 + 2*8192) * 4;
    if (!smem_set) {
        cudaFuncSetAttribute(prep_kernel, cudaFuncAttributeMaxDynamicSharedMemorySize, prep_smem);
        smem_set = 1;
    }

    dim3 g1(T_/8, B_);
    prep_kernel<<<g1, 256, prep_smem>>>(input, demo, Wt, Wx, Wd, bh);

    dim3 g2(T_/4, B_);
    strip_kernel<<<g2, 256>>>(input, Wa, ba, out_e, out_v);
}

// round 13
// speedup vs baseline: 1.4629x; 1.4629x over previous
#include <cuda_runtime.h>
#include <cuda_pipeline.h>
#include <math_constants.h>

#define B_ 4
#define T_ 512
#define D_ 128
#define H_ 64
#define KP (H_ + 4)   // padded K row stride (conflict-free f4 phases)

__device__ float g_Q[B_*T_*H_];
__device__ float g_K[B_*T_*H_];

__device__ __forceinline__ float tanh_fast(float x) {
    float y;
    asm("tanh.approx.f32 %0, %1;" : "=f"(y) : "f"(x));
    return y;
}

// ---------------------------------------------------------------------------
// Kernel 1: Q/K' prep (R8 version, unchanged control). grid (T/8,B)=256.
// ---------------------------------------------------------------------------
__global__ __launch_bounds__(256) void prep_kernel(
    const float* __restrict__ input, const float* __restrict__ demo,
    const float* __restrict__ Wt, const float* __restrict__ Wx,
    const float* __restrict__ Wd, const float* __restrict__ bh)
{
    extern __shared__ float dyn[];
    float* sx  = dyn;           // [8][128]
    float* sWt = dyn + 1024;    // [128][64]
    float* sWx = dyn + 9216;    // [128][64]

    const int b   = blockIdx.y;
    const int t0  = blockIdx.x * 8;
    const int tid = threadIdx.x;
    const int h   = tid & 63;
    const int rg  = tid >> 6;

    {
        const float4* gin = (const float4*)(input + (size_t)(b*T_ + t0)*D_);
        __pipeline_memcpy_async(&((float4*)sx)[tid], &gin[tid], 16);
        const float4* gt = (const float4*)Wt;
        const float4* gx = (const float4*)Wx;
        #pragma unroll
        for (int i = 0; i < 8; i++) {
            int idx = tid + 256*i;
            __pipeline_memcpy_async(&((float4*)sWt)[idx], &gt[idx], 16);
            __pipeline_memcpy_async(&((float4*)sWx)[idx], &gx[idx], 16);
        }
        __pipeline_commit();
    }

    float dd = bh[h];
    #pragma unroll
    for (int j = 0; j < 12; j++) dd = fmaf(demo[b*12 + j], Wd[j*H_ + h], dd);

    __pipeline_wait_prior(0);
    __syncthreads();

    float aq0=0.f, ak0=0.f, aq1=0.f, ak1=0.f;
    #pragma unroll 16
    for (int d = 0; d < D_; d++) {
        float wt = sWt[d*H_ + h];
        float wx = sWx[d*H_ + h];
        float x0 = sx[(rg    )*D_ + d];
        float x1 = sx[(rg + 4)*D_ + d];
        aq0 = fmaf(x0, wt, aq0);
        ak0 = fmaf(x0, wx, ak0);
        aq1 = fmaf(x1, wt, aq1);
        ak1 = fmaf(x1, wx, ak1);
    }

    const size_t o0 = (size_t)(b*T_ + t0 + rg    )*H_ + h;
    const size_t o1 = (size_t)(b*T_ + t0 + rg + 4)*H_ + h;
    g_Q[o0] = aq0;  g_K[o0] = ak0 + dd;
    g_Q[o1] = aq1;  g_K[o1] = ak1 + dd;
}

// ---------------------------------------------------------------------------
// Kernel 2: FUSED strip kernel (R11 TT=8 shape) + DOUBLE-BUFFERED chunks.
// CTA per (b, 8-row t-strip), 256 threads, grid (64,4)=256 heavy-first.
// sK[2] buffers serve K chunks (score) then input chunks (v).
// ---------------------------------------------------------------------------
__global__ __launch_bounds__(256) void strip_kernel(
    const float* __restrict__ input,
    const float* __restrict__ Wa, const float* __restrict__ ba,
    float* __restrict__ out_e, float* __restrict__ out_v)
{
    __shared__ float sQ[8][H_];        // 2 KB
    __shared__ float sWa[H_];
    __shared__ float sK[2][64][KP];    // 34.8 KB double-buffered
    __shared__ float sSc[8][T_];       // 16 KB

    const int b    = blockIdx.y;
    const int i_s  = 63 - (int)blockIdx.x;     // heavy first
    const int t0   = i_s * 8;
    const int tid  = threadIdx.x;

    {   // Q strip + Wa
        if (tid < 128) {
            const float4* gq = (const float4*)(g_Q + (size_t)(b*T_ + t0)*H_);
            ((float4*)sQ)[tid] = gq[tid];
        } else if (tid < 128 + H_/4) {
            ((float4*)sWa)[tid - 128] = ((const float4*)Wa)[tid - 128];
        }
    }
    const float bav = ba[0];

    // ---- Phase 1: causal scores over nk 64-s chunks, double-buffered ----
    const int nk = i_s/8 + 1;          // 1..8
    const int sl = tid & 63;
    const int tg = tid >> 6;           // rows tg and tg+4
    const int j4 = tid & 15;
    const int r4 = tid >> 4;           // 16 K rows per pass

    const float4* kbase = (const float4*)(g_K + (size_t)(b*T_)*H_);

    // prefetch chunk 0 -> buf 0
    #pragma unroll
    for (int ii = 0; ii < 4; ii++) {
        int r = r4 + 16*ii;
        __pipeline_memcpy_async(&sK[0][r][4*j4], &kbase[(size_t)r*16 + j4], 16);
    }
    __pipeline_commit();

    for (int c = 0; c < nk; c++) {
        if (c + 1 < nk) {
            const float4* kp = kbase + (size_t)(c+1)*64*16;
            const int buf = (c+1) & 1;
            #pragma unroll
            for (int ii = 0; ii < 4; ii++) {
                int r = r4 + 16*ii;
                __pipeline_memcpy_async(&sK[buf][r][4*j4], &kp[(size_t)r*16 + j4], 16);
            }
            __pipeline_commit();
            __pipeline_wait_prior(1);
        } else {
            __pipeline_wait_prior(0);
        }
        __syncthreads();   // chunk c visible (first iter also covers sQ/sWa)

        const float (*kb)[KP] = sK[c & 1];
        float a0=0.f,a1=0.f,a2=0.f,a3=0.f,b0=0.f,b1=0.f,b2=0.f,b3=0.f;
        #pragma unroll
        for (int h4 = 0; h4 < H_/4; h4++) {
            float4 k  = *(const float4*)&kb[sl][4*h4];
            float4 w  = ((const float4*)sWa)[h4];
            float4 q0 = ((const float4*)sQ[tg])[h4];
            float4 q1 = ((const float4*)sQ[tg+4])[h4];
            a0 = fmaf(w.x, tanh_fast(q0.x + k.x), a0);
            a1 = fmaf(w.y, tanh_fast(q0.y + k.y), a1);
            a2 = fmaf(w.z, tanh_fast(q0.z + k.z), a2);
            a3 = fmaf(w.w, tanh_fast(q0.w + k.w), a3);
            b0 = fmaf(w.x, tanh_fast(q1.x + k.x), b0);
            b1 = fmaf(w.y, tanh_fast(q1.y + k.y), b1);
            b2 = fmaf(w.z, tanh_fast(q1.z + k.z), b2);
            b3 = fmaf(w.w, tanh_fast(q1.w + k.w), b3);
        }
        sSc[tg  ][c*64 + sl] = bav + ((a0 + a1) + (a2 + a3));
        sSc[tg+4][c*64 + sl] = bav + ((b0 + b1) + (b2 + b3));
        __syncthreads();   // readers of buf (c&1) done before c+2 prefetch
    }

    // prefetch v-chunk 0 into sK[0] (score pipeline fully drained above)
    const int nc = t0/32 + 1;          // 1..16
    {
        const float4* gin = (const float4*)(input + (size_t)(b*T_)*D_);
        #pragma unroll
        for (int ii = 0; ii < 4; ii++)
            __pipeline_memcpy_async(&((float4*)&sK[0][0][0])[tid + 256*ii], &gin[tid + 256*ii], 16);
        __pipeline_commit();
    }

    // ---- Phase 2: causal softmax per warp-row ----
    const int w    = tid >> 5;
    const int lane = tid & 31;
    const int t    = t0 + w;
    {
        float vals[T_/32];
        float m = -CUDART_INF_F;
        #pragma unroll
        for (int i = 0; i < T_/32; i++) {
            int s = lane + 32*i;
            vals[i] = (s <= t) ? sSc[w][s] : -CUDART_INF_F;
            m = fmaxf(m, vals[i]);
        }
        #pragma unroll
        for (int off = 16; off; off >>= 1) m = fmaxf(m, __shfl_xor_sync(0xffffffffu, m, off));
        float sum = 0.f;
        #pragma unroll
        for (int i = 0; i < T_/32; i++) {
            float e = __expf(vals[i] - m);   // -inf -> 0
            vals[i] = e;
            sum += e;
        }
        #pragma unroll
        for (int off = 16; off; off >>= 1) sum += __shfl_xor_sync(0xffffffffu, sum, off);
        float inv = 1.f / (sum + 1e-7f);
        float* ge = out_e + ((size_t)(b*T_ + t))*T_;
        #pragma unroll
        for (int i = 0; i < T_/32; i++) {
            int s = lane + 32*i;
            float p = vals[i] * inv;         // 0 for s>t
            ge[s]     = p;
            sSc[w][s] = p;                   // own-warp row, no block sync needed
        }
    }

    // ---- Phase 3: v = P @ input, double-buffered input chunks ----
    float4 acc = make_float4(0.f,0.f,0.f,0.f);
    for (int c = 0; c < nc; c++) {
        if (c + 1 < nc) {
            const float4* gin = (const float4*)(input + (size_t)(b*T_ + (c+1)*32)*D_);
            float* dst = &sK[(c+1)&1][0][0];
            #pragma unroll
            for (int ii = 0; ii < 4; ii++)
                __pipeline_memcpy_async(&((float4*)dst)[tid + 256*ii], &gin[tid + 256*ii], 16);
            __pipeline_commit();
            __pipeline_wait_prior(1);
        } else {
            __pipeline_wait_prior(0);
        }
        __syncthreads();   // chunk c visible

        const float* sIn = &sK[c&1][0][0];
        #pragma unroll
        for (int s = 0; s < 32; s++) {
            float p = sSc[w][c*32 + s];
            float4 x = ((const float4*)(sIn + s*D_))[lane];
            acc.x = fmaf(p, x.x, acc.x);
            acc.y = fmaf(p, x.y, acc.y);
            acc.z = fmaf(p, x.z, acc.z);
            acc.w = fmaf(p, x.w, acc.w);
        }
        __syncthreads();   // readers of buf (c&1) done before c+2 prefetch
    }
    ((float4*)(out_v + (size_t)(b*T_ + t)*D_))[lane] = acc;
}

// ---------------------------------------------------------------------------
extern "C" void kernel_launch(void* const* d_in, const int* in_sizes, int n_in,
                              void* d_out, int out_size)
{
    const float* input = (const float*)d_in[0];
    const float* demo  = (const float*)d_in[1];
    const float* Wt    = (const float*)d_in[2];
    const float* Wx    = (const float*)d_in[3];
    const float* Wd    = (const float*)d_in[4];
    const float* bh    = (const float*)d_in[5];
    const float* Wa    = (const float*)d_in[6];
    const float* ba    = (const float*)d_in[7];

    float* out_v = (float*)d_out;                   // [B,T,D]
    float* out_e = out_v + (size_t)B_ * T_ * D_;    // [B,T,T]

    static int smem_set = 0;
    const int prep_smem = (1024 + 2*8192) * 4;
    if (!smem_set) {
        cudaFuncSetAttribute(prep_kernel, cudaFuncAttributeMaxDynamicSharedMemorySize, prep_smem);
        smem_set = 1;
    }

    dim3 g1(T_/8, B_);
    prep_kernel<<<g1, 256, prep_smem>>>(input, demo, Wt, Wx, Wd, bh);

    dim3 g2(T_/8, B_);
    strip_kernel<<<g2, 256>>>(input, Wa, ba, out_e, out_v);
}

// round 15
// speedup vs baseline: 1.6735x; 1.1440x over previous
#include <cuda_runtime.h>
#include <cuda_pipeline.h>
#include <math_constants.h>

#define B_ 4
#define T_ 512
#define D_ 128
#define H_ 64
#define KP (H_ + 4)   // padded K row stride (conflict-free f4 phases)

__device__ float g_Q[B_*T_*H_];
__device__ float g_K[B_*T_*H_];

__device__ __forceinline__ float tanh_fast(float x) {
    float y;
    asm("tanh.approx.f32 %0, %1;" : "=f"(y) : "f"(x));
    return y;
}

// ---------------------------------------------------------------------------
// Kernel 1: Q/K' prep, h-SPLIT. CTA = 8 t-rows x 32 h-cols.
// grid (T/8, 2, B) = 512 CTAs, 36KB smem -> 6 CTAs/SM cap (~3.5 resident).
// Per-CTA W traffic is HALF of the full-h version (stages only its h-half).
// ---------------------------------------------------------------------------
__global__ __launch_bounds__(256) void prep_kernel(
    const float* __restrict__ input, const float* __restrict__ demo,
    const float* __restrict__ Wt, const float* __restrict__ Wx,
    const float* __restrict__ Wd, const float* __restrict__ bh)
{
    extern __shared__ float dyn[];
    float* sx  = dyn;           // [8][128]   1024 floats
    float* sWt = dyn + 1024;    // [128][32]  4096 floats
    float* sWx = dyn + 5120;    // [128][32]  4096 floats

    const int b    = blockIdx.z;
    const int half = blockIdx.y;       // h-half: 0 or 1
    const int t0   = blockIdx.x * 8;
    const int tid  = threadIdx.x;
    const int h32  = tid & 31;         // lane = h within half
    const int rg   = tid >> 5;         // 0..7 -> this thread's row
    const int h    = half*32 + h32;

    {   // stage 8 input rows (256 f4) + W half-columns (1024 f4 each)
        const float4* gin = (const float4*)(input + (size_t)(b*T_ + t0)*D_);
        __pipeline_memcpy_async(&((float4*)sx)[tid], &gin[tid], 16);
        const float4* gt = (const float4*)Wt;   // row d = 16 f4; half -> 8 f4
        const float4* gx = (const float4*)Wx;
        #pragma unroll
        for (int i = 0; i < 4; i++) {
            int idx = tid + 256*i;              // 0..1023
            int d   = idx >> 3;                 // W row
            int j   = idx & 7;                  // f4 within half-row
            __pipeline_memcpy_async(&((float4*)sWt)[idx], &gt[d*16 + half*8 + j], 16);
            __pipeline_memcpy_async(&((float4*)sWx)[idx], &gx[d*16 + half*8 + j], 16);
        }
        __pipeline_commit();
    }

    float dd = bh[h];
    #pragma unroll
    for (int j = 0; j < 12; j++) dd = fmaf(demo[b*12 + j], Wd[j*H_ + h], dd);

    __pipeline_wait_prior(0);
    __syncthreads();

    float aq = 0.f, ak = 0.f;
    #pragma unroll 16
    for (int d = 0; d < D_; d++) {
        float x = sx[rg*D_ + d];               // broadcast within warp
        aq = fmaf(x, sWt[d*32 + h32], aq);     // conflict-free (lane = h32)
        ak = fmaf(x, sWx[d*32 + h32], ak);
    }

    const size_t o = (size_t)(b*T_ + t0 + rg)*H_ + h;
    g_Q[o] = aq;
    g_K[o] = ak + dd;
}

// ---------------------------------------------------------------------------
// Kernel 2: FUSED strip kernel (R13, unchanged). TT=8, double-buffered.
// ---------------------------------------------------------------------------
__global__ __launch_bounds__(256) void strip_kernel(
    const float* __restrict__ input,
    const float* __restrict__ Wa, const float* __restrict__ ba,
    float* __restrict__ out_e, float* __restrict__ out_v)
{
    __shared__ float sQ[8][H_];        // 2 KB
    __shared__ float sWa[H_];
    __shared__ float sK[2][64][KP];    // 34.8 KB double-buffered
    __shared__ float sSc[8][T_];       // 16 KB

    const int b    = blockIdx.y;
    const int i_s  = 63 - (int)blockIdx.x;     // heavy first
    const int t0   = i_s * 8;
    const int tid  = threadIdx.x;

    {
        if (tid < 128) {
            const float4* gq = (const float4*)(g_Q + (size_t)(b*T_ + t0)*H_);
            ((float4*)sQ)[tid] = gq[tid];
        } else if (tid < 128 + H_/4) {
            ((float4*)sWa)[tid - 128] = ((const float4*)Wa)[tid - 128];
        }
    }
    const float bav = ba[0];

    const int nk = i_s/8 + 1;
    const int sl = tid & 63;
    const int tg = tid >> 6;
    const int j4 = tid & 15;
    const int r4 = tid >> 4;

    const float4* kbase = (const float4*)(g_K + (size_t)(b*T_)*H_);

    #pragma unroll
    for (int ii = 0; ii < 4; ii++) {
        int r = r4 + 16*ii;
        __pipeline_memcpy_async(&sK[0][r][4*j4], &kbase[(size_t)r*16 + j4], 16);
    }
    __pipeline_commit();

    for (int c = 0; c < nk; c++) {
        if (c + 1 < nk) {
            const float4* kp = kbase + (size_t)(c+1)*64*16;
            const int buf = (c+1) & 1;
            #pragma unroll
            for (int ii = 0; ii < 4; ii++) {
                int r = r4 + 16*ii;
                __pipeline_memcpy_async(&sK[buf][r][4*j4], &kp[(size_t)r*16 + j4], 16);
            }
            __pipeline_commit();
            __pipeline_wait_prior(1);
        } else {
            __pipeline_wait_prior(0);
        }
        __syncthreads();

        const float (*kb)[KP] = sK[c & 1];
        float a0=0.f,a1=0.f,a2=0.f,a3=0.f,b0=0.f,b1=0.f,b2=0.f,b3=0.f;
        #pragma unroll
        for (int h4 = 0; h4 < H_/4; h4++) {
            float4 k  = *(const float4*)&kb[sl][4*h4];
            float4 w  = ((const float4*)sWa)[h4];
            float4 q0 = ((const float4*)sQ[tg])[h4];
            float4 q1 = ((const float4*)sQ[tg+4])[h4];
            a0 = fmaf(w.x, tanh_fast(q0.x + k.x), a0);
            a1 = fmaf(w.y, tanh_fast(q0.y + k.y), a1);
            a2 = fmaf(w.z, tanh_fast(q0.z + k.z), a2);
            a3 = fmaf(w.w, tanh_fast(q0.w + k.w), a3);
            b0 = fmaf(w.x, tanh_fast(q1.x + k.x), b0);
            b1 = fmaf(w.y, tanh_fast(q1.y + k.y), b1);
            b2 = fmaf(w.z, tanh_fast(q1.z + k.z), b2);
            b3 = fmaf(w.w, tanh_fast(q1.w + k.w), b3);
        }
        sSc[tg  ][c*64 + sl] = bav + ((a0 + a1) + (a2 + a3));
        sSc[tg+4][c*64 + sl] = bav + ((b0 + b1) + (b2 + b3));
        __syncthreads();
    }

    const int nc = t0/32 + 1;
    {
        const float4* gin = (const float4*)(input + (size_t)(b*T_)*D_);
        #pragma unroll
        for (int ii = 0; ii < 4; ii++)
            __pipeline_memcpy_async(&((float4*)&sK[0][0][0])[tid + 256*ii], &gin[tid + 256*ii], 16);
        __pipeline_commit();
    }

    const int w    = tid >> 5;
    const int lane = tid & 31;
    const int t    = t0 + w;
    {
        float vals[T_/32];
        float m = -CUDART_INF_F;
        #pragma unroll
        for (int i = 0; i < T_/32; i++) {
            int s = lane + 32*i;
            vals[i] = (s <= t) ? sSc[w][s] : -CUDART_INF_F;
            m = fmaxf(m, vals[i]);
        }
        #pragma unroll
        for (int off = 16; off; off >>= 1) m = fmaxf(m, __shfl_xor_sync(0xffffffffu, m, off));
        float sum = 0.f;
        #pragma unroll
        for (int i = 0; i < T_/32; i++) {
            float e = __expf(vals[i] - m);
            vals[i] = e;
            sum += e;
        }
        #pragma unroll
        for (int off = 16; off; off >>= 1) sum += __shfl_xor_sync(0xffffffffu, sum, off);
        float inv = 1.f / (sum + 1e-7f);
        float* ge = out_e + ((size_t)(b*T_ + t))*T_;
        #pragma unroll
        for (int i = 0; i < T_/32; i++) {
            int s = lane + 32*i;
            float p = vals[i] * inv;
            ge[s]     = p;
            sSc[w][s] = p;
        }
    }

    float4 acc = make_float4(0.f,0.f,0.f,0.f);
    for (int c = 0; c < nc; c++) {
        if (c + 1 < nc) {
            const float4* gin = (const float4*)(input + (size_t)(b*T_ + (c+1)*32)*D_);
            float* dst = &sK[(c+1)&1][0][0];
            #pragma unroll
            for (int ii = 0; ii < 4; ii++)
                __pipeline_memcpy_async(&((float4*)dst)[tid + 256*ii], &gin[tid + 256*ii], 16);
            __pipeline_commit();
            __pipeline_wait_prior(1);
        } else {
            __pipeline_wait_prior(0);
        }
        __syncthreads();

        const float* sIn = &sK[c&1][0][0];
        #pragma unroll
        for (int s = 0; s < 32; s++) {
            float p = sSc[w][c*32 + s];
            float4 x = ((const float4*)(sIn + s*D_))[lane];
            acc.x = fmaf(p, x.x, acc.x);
            acc.y = fmaf(p, x.y, acc.y);
            acc.z = fmaf(p, x.z, acc.z);
            acc.w = fmaf(p, x.w, acc.w);
        }
        __syncthreads();
    }
    ((float4*)(out_v + (size_t)(b*T_ + t)*D_))[lane] = acc;
}

// ---------------------------------------------------------------------------
extern "C" void kernel_launch(void* const* d_in, const int* in_sizes, int n_in,
                              void* d_out, int out_size)
{
    const float* input = (const float*)d_in[0];
    const float* demo  = (const float*)d_in[1];
    const float* Wt    = (const float*)d_in[2];
    const float* Wx    = (const float*)d_in[3];
    const float* Wd    = (const float*)d_in[4];
    const float* bh    = (const float*)d_in[5];
    const float* Wa    = (const float*)d_in[6];
    const float* ba    = (const float*)d_in[7];

    float* out_v = (float*)d_out;                   // [B,T,D]
    float* out_e = out_v + (size_t)B_ * T_ * D_;    // [B,T,T]

    static int smem_set = 0;
    const int prep_smem = (1024 + 2*4096) * 4;      // 36,864 B
    if (!smem_set) {
        cudaFuncSetAttribute(prep_kernel, cudaFuncAttributeMaxDynamicSharedMemorySize, prep_smem);
        smem_set = 1;
    }

    dim3 g1(T_/8, 2, B_);
    prep_kernel<<<g1, 256, prep_smem>>>(input, demo, Wt, Wx, Wd, bh);

    dim3 g2(T_/8, B_);
    strip_kernel<<<g2, 256>>>(input, Wa, ba, out_e, out_v);
}

// round 17
// speedup vs baseline: 1.7509x; 1.0463x over previous
#include <cuda_runtime.h>
#include <cuda_pipeline.h>
#include <math_constants.h>

#define B_ 4
#define T_ 512
#define D_ 128
#define H_ 64
#define KP (H_ + 4)   // padded K row stride (conflict-free f4 phases)

__device__ float g_K[B_*T_*H_];

__device__ __forceinline__ float tanh_fast(float x) {
    float y;
    asm("tanh.approx.f32 %0, %1;" : "=f"(y) : "f"(x));
    return y;
}

// ---------------------------------------------------------------------------
// Kernel 1: K' prep ONLY (K' = input@Wx + demo@Wd + bh). 8 t-rows/CTA,
// grid (T/8,B)=256, Wx staged once (32KB) via cp.async.
// ---------------------------------------------------------------------------
__global__ __launch_bounds__(256) void prepk_kernel(
    const float* __restrict__ input, const float* __restrict__ demo,
    const float* __restrict__ Wx, const float* __restrict__ Wd,
    const float* __restrict__ bh)
{
    extern __shared__ float dyn[];
    float* sx  = dyn;           // [8][128]   1024 floats
    float* sWx = dyn + 1024;    // [128][64]  8192 floats

    const int b   = blockIdx.y;
    const int t0  = blockIdx.x * 8;
    const int tid = threadIdx.x;
    const int h   = tid & 63;
    const int rg  = tid >> 6;          // rows rg, rg+4

    {
        const float4* gin = (const float4*)(input + (size_t)(b*T_ + t0)*D_);
        __pipeline_memcpy_async(&((float4*)sx)[tid], &gin[tid], 16);
        const float4* gx = (const float4*)Wx;
        #pragma unroll
        for (int i = 0; i < 8; i++) {
            int idx = tid + 256*i;
            __pipeline_memcpy_async(&((float4*)sWx)[idx], &gx[idx], 16);
        }
        __pipeline_commit();
    }

    float dd = bh[h];
    #pragma unroll
    for (int j = 0; j < 12; j++) dd = fmaf(demo[b*12 + j], Wd[j*H_ + h], dd);

    __pipeline_wait_prior(0);
    __syncthreads();

    float ak0 = 0.f, ak1 = 0.f;
    #pragma unroll 16
    for (int d = 0; d < D_; d++) {
        float wx = sWx[d*H_ + h];
        ak0 = fmaf(sx[(rg    )*D_ + d], wx, ak0);
        ak1 = fmaf(sx[(rg + 4)*D_ + d], wx, ak1);
    }

    g_K[(size_t)(b*T_ + t0 + rg    )*H_ + h] = ak0 + dd;
    g_K[(size_t)(b*T_ + t0 + rg + 4)*H_ + h] = ak1 + dd;
}

// ---------------------------------------------------------------------------
// Kernel 2: FUSED strip kernel (R13 body) + local Q compute + PDL.
// Pre-sync work (input stage, Q = x@Wt via L2 LDG, Wa) overlaps prepk.
// cudaGridDependencySynchronize() guards the first g_K read.
// ---------------------------------------------------------------------------
__global__ __launch_bounds__(256) void strip_kernel(
    const float* __restrict__ input, const float* __restrict__ Wt,
    const float* __restrict__ Wa, const float* __restrict__ ba,
    float* __restrict__ out_e, float* __restrict__ out_v)
{
    __shared__ float sQ[8][H_];        // 2 KB
    __shared__ float sWa[H_];
    __shared__ float sK[2][64][KP];    // 34.8 KB double-buffered
    __shared__ float sSc[8][T_];       // 16 KB (first 4KB doubles as x scratch)

    const int b    = blockIdx.y;
    const int i_s  = 63 - (int)blockIdx.x;     // heavy first
    const int t0   = i_s * 8;
    const int tid  = threadIdx.x;

    // ---- Phase 0 (overlaps prepk under PDL): stage x rows, compute Q ----
    float* sxq = &sSc[0][0];           // 1024-float scratch
    {
        const float4* gin = (const float4*)(input + (size_t)(b*T_ + t0)*D_);
        ((float4*)sxq)[tid] = gin[tid];
        if (tid < H_/4) ((float4*)sWa)[tid] = ((const float4*)Wa)[tid];
    }
    __syncthreads();
    {
        const int h  = tid & 63;
        const int rg = tid >> 6;       // rows rg, rg+4
        float aq0 = 0.f, aq1 = 0.f;
        #pragma unroll 8
        for (int d = 0; d < D_; d++) {
            float wt = __ldg(&Wt[d*H_ + h]);
            aq0 = fmaf(sxq[rg*D_ + d],     wt, aq0);
            aq1 = fmaf(sxq[(rg+4)*D_ + d], wt, aq1);
        }
        sQ[rg  ][h] = aq0;
        sQ[rg+4][h] = aq1;
    }
    const float bav = ba[0];

    // ---- wait for prepk's g_K before any K access ----
    cudaGridDependencySynchronize();

    // ---- Phase 1: causal scores over nk 64-s chunks, double-buffered ----
    const int nk = i_s/8 + 1;          // 1..8
    const int sl = tid & 63;
    const int tg = tid >> 6;           // rows tg and tg+4
    const int j4 = tid & 15;
    const int r4 = tid >> 4;

    const float4* kbase = (const float4*)(g_K + (size_t)(b*T_)*H_);

    #pragma unroll
    for (int ii = 0; ii < 4; ii++) {
        int r = r4 + 16*ii;
        __pipeline_memcpy_async(&sK[0][r][4*j4], &kbase[(size_t)r*16 + j4], 16);
    }
    __pipeline_commit();

    for (int c = 0; c < nk; c++) {
        if (c + 1 < nk) {
            const float4* kp = kbase + (size_t)(c+1)*64*16;
            const int buf = (c+1) & 1;
            #pragma unroll
            for (int ii = 0; ii < 4; ii++) {
                int r = r4 + 16*ii;
                __pipeline_memcpy_async(&sK[buf][r][4*j4], &kp[(size_t)r*16 + j4], 16);
            }
            __pipeline_commit();
            __pipeline_wait_prior(1);
        } else {
            __pipeline_wait_prior(0);
        }
        __syncthreads();   // chunk c + sQ stores visible to all

        const float (*kb)[KP] = sK[c & 1];
        float a0=0.f,a1=0.f,a2=0.f,a3=0.f,b0=0.f,b1=0.f,b2=0.f,b3=0.f;
        #pragma unroll
        for (int h4 = 0; h4 < H_/4; h4++) {
            float4 k  = *(const float4*)&kb[sl][4*h4];
            float4 w  = ((const float4*)sWa)[h4];
            float4 q0 = ((const float4*)sQ[tg])[h4];
            float4 q1 = ((const float4*)sQ[tg+4])[h4];
            a0 = fmaf(w.x, tanh_fast(q0.x + k.x), a0);
            a1 = fmaf(w.y, tanh_fast(q0.y + k.y), a1);
            a2 = fmaf(w.z, tanh_fast(q0.z + k.z), a2);
            a3 = fmaf(w.w, tanh_fast(q0.w + k.w), a3);
            b0 = fmaf(w.x, tanh_fast(q1.x + k.x), b0);
            b1 = fmaf(w.y, tanh_fast(q1.y + k.y), b1);
            b2 = fmaf(w.z, tanh_fast(q1.z + k.z), b2);
            b3 = fmaf(w.w, tanh_fast(q1.w + k.w), b3);
        }
        sSc[tg  ][c*64 + sl] = bav + ((a0 + a1) + (a2 + a3));
        sSc[tg+4][c*64 + sl] = bav + ((b0 + b1) + (b2 + b3));
        __syncthreads();
    }

    const int nc = t0/32 + 1;
    {
        const float4* gin = (const float4*)(input + (size_t)(b*T_)*D_);
        #pragma unroll
        for (int ii = 0; ii < 4; ii++)
            __pipeline_memcpy_async(&((float4*)&sK[0][0][0])[tid + 256*ii], &gin[tid + 256*ii], 16);
        __pipeline_commit();
    }

    // ---- Phase 2: causal softmax per warp-row ----
    const int w    = tid >> 5;
    const int lane = tid & 31;
    const int t    = t0 + w;
    {
        float vals[T_/32];
        float m = -CUDART_INF_F;
        #pragma unroll
        for (int i = 0; i < T_/32; i++) {
            int s = lane + 32*i;
            vals[i] = (s <= t) ? sSc[w][s] : -CUDART_INF_F;
            m = fmaxf(m, vals[i]);
        }
        #pragma unroll
        for (int off = 16; off; off >>= 1) m = fmaxf(m, __shfl_xor_sync(0xffffffffu, m, off));
        float sum = 0.f;
        #pragma unroll
        for (int i = 0; i < T_/32; i++) {
            float e = __expf(vals[i] - m);   // -inf -> 0
            vals[i] = e;
            sum += e;
        }
        #pragma unroll
        for (int off = 16; off; off >>= 1) sum += __shfl_xor_sync(0xffffffffu, sum, off);
        float inv = 1.f / (sum + 1e-7f);
        float* ge = out_e + ((size_t)(b*T_ + t))*T_;
        #pragma unroll
        for (int i = 0; i < T_/32; i++) {
            int s = lane + 32*i;
            float p = vals[i] * inv;
            ge[s]     = p;
            sSc[w][s] = p;
        }
    }

    // ---- Phase 3: v = P @ input, double-buffered input chunks ----
    float4 acc = make_float4(0.f,0.f,0.f,0.f);
    for (int c = 0; c < nc; c++) {
        if (c + 1 < nc) {
            const float4* gin = (const float4*)(input + (size_t)(b*T_ + (c+1)*32)*D_);
            float* dst = &sK[(c+1)&1][0][0];
            #pragma unroll
            for (int ii = 0; ii < 4; ii++)
                __pipeline_memcpy_async(&((float4*)dst)[tid + 256*ii], &gin[tid + 256*ii], 16);
            __pipeline_commit();
            __pipeline_wait_prior(1);
        } else {
            __pipeline_wait_prior(0);
        }
        __syncthreads();

        const float* sIn = &sK[c&1][0][0];
        #pragma unroll
        for (int s = 0; s < 32; s++) {
            float p = sSc[w][c*32 + s];
            float4 x = ((const float4*)(sIn + s*D_))[lane];
            acc.x = fmaf(p, x.x, acc.x);
            acc.y = fmaf(p, x.y, acc.y);
            acc.z = fmaf(p, x.z, acc.z);
            acc.w = fmaf(p, x.w, acc.w);
        }
        __syncthreads();
    }
    ((float4*)(out_v + (size_t)(b*T_ + t)*D_))[lane] = acc;
}

// ---------------------------------------------------------------------------
extern "C" void kernel_launch(void* const* d_in, const int* in_sizes, int n_in,
                              void* d_out, int out_size)
{
    const float* input = (const float*)d_in[0];
    const float* demo  = (const float*)d_in[1];
    const float* Wt    = (const float*)d_in[2];
    const float* Wx    = (const float*)d_in[3];
    const float* Wd    = (const float*)d_in[4];
    const float* bh    = (const float*)d_in[5];
    const float* Wa    = (const float*)d_in[6];
    const float* ba    = (const float*)d_in[7];

    float* out_v = (float*)d_out;                   // [B,T,D]
    float* out_e = out_v + (size_t)B_ * T_ * D_;    // [B,T,T]

    static int smem_set = 0;
    const int prep_smem = (1024 + 8192) * 4;        // 36,864 B
    if (!smem_set) {
        cudaFuncSetAttribute(prepk_kernel, cudaFuncAttributeMaxDynamicSharedMemorySize, prep_smem);
        smem_set = 1;
    }

    dim3 g1(T_/8, B_);
    prepk_kernel<<<g1, 256, prep_smem>>>(input, demo, Wx, Wd, bh);

    // strip with programmatic dependent launch: pre-sync phase overlaps prepk
    cudaLaunchConfig_t cfg = {};
    cfg.gridDim  = dim3(T_/8, B_);
    cfg.blockDim = dim3(256);
    cfg.dynamicSmemBytes = 0;
    cfg.stream = 0;
    cudaLaunchAttribute attrs[1];
    attrs[0].id = cudaLaunchAttributeProgrammaticStreamSerialization;
    attrs[0].val.programmaticStreamSerializationAllowed = 1;
    cfg.attrs = attrs;
    cfg.numAttrs = 1;
    cudaLaunchKernelEx(&cfg, strip_kernel, input, Wt, Wa, ba, out_e, out_v);
}